// round 2
// baseline (speedup 1.0000x reference)
#include <cuda_runtime.h>

// ---------------- problem constants ----------------
#define L_   8
#define H_   256
#define W_   448
#define KL_  2
#define KH_  18
#define KW_  32
#define K_   1152              // KL*KH*KW
#define HW_  (H_*W_)           // 114688
#define NPIX (L_*HW_)          // 917504
#define CMAX 840               // max pixels per cell: 4 * 15 * 14

#define T_SCALE   0.625f                       // Kl/(0.4*L)
#define YX_SCALE  ((float)0.17857142857142858) // max(Kh/(0.4*H), Kw/(0.4*W))
#define LAB_SCALE 0.26f

// ---------------- device scratch (no allocs allowed) ----------------
__device__ float g_pF[K_*6*CMAX];   // cell-blocked pixel features [k][c][p] (~23MB)
__device__ float g_spFeat[K_*6];    // superpixel features [k][c]
__device__ float g_part[K_*189];    // per-block partial sums [k][j*7+c] (c=6 -> weight)

__device__ __forceinline__ float warpSum(float v){
#pragma unroll
    for (int o = 16; o > 0; o >>= 1) v += __shfl_down_sync(0xffffffffu, v, o);
    return v;
}

// cell geometry: t in [4kl,4kl+4), y in [y0,y0+ch), x in [14kw,14kw+14)
__device__ __forceinline__ void cellGeom(int k, int& kl, int& kh, int& kw, int& y0, int& ch){
    kl = k / (KH_*KW_);
    kh = (k / KW_) % KH_;
    kw = k % KW_;
    y0 = (256*kh + 17) / 18;
    int y1 = (256*(kh+1) + 17) / 18;
    ch = y1 - y0;  // 14 or 15
}

// ---------------- kernel 1: pFeat + blocked copy + sp_init mean ----------------
__global__ void __launch_bounds__(256) pa_kernel(const float* __restrict__ lab,
                                                 float* __restrict__ outPF){
    int k = blockIdx.x, tid = threadIdx.x;
    int kl, kh, kw, y0, ch;
    cellGeom(k, kl, kh, kw, y0, ch);
    int P = 56 * ch;  // 4 * ch * 14

    float s0=0.f,s1=0.f,s2=0.f,s3=0.f,s4=0.f,s5=0.f;
    float* gp = &g_pF[(size_t)k*6*CMAX];
#pragma unroll 1
    for (int p = tid; p < P; p += 256){
        int lx = p % 14, q = p / 14, ly = q % ch, lt = q / ch;
        int t = 4*kl + lt, y = y0 + ly, x = 14*kw + lx;
        int pix = t*HW_ + y*W_ + x;
        float f0 = T_SCALE  * (float)t;
        float f1 = YX_SCALE * (float)y;
        float f2 = YX_SCALE * (float)x;
        float f3 = LAB_SCALE * lab[pix];
        float f4 = LAB_SCALE * lab[NPIX + pix];
        float f5 = LAB_SCALE * lab[2*NPIX + pix];
        outPF[pix]          = f0;
        outPF[NPIX+pix]     = f1;
        outPF[2*NPIX+pix]   = f2;
        outPF[3*NPIX+pix]   = f3;
        outPF[4*NPIX+pix]   = f4;
        outPF[5*NPIX+pix]   = f5;
        gp[p]          = f0;
        gp[CMAX+p]     = f1;
        gp[2*CMAX+p]   = f2;
        gp[3*CMAX+p]   = f3;
        gp[4*CMAX+p]   = f4;
        gp[5*CMAX+p]   = f5;
        s0+=f0; s1+=f1; s2+=f2; s3+=f3; s4+=f4; s5+=f5;
    }
    __shared__ float red[6][8];
    int wid = tid >> 5, lane = tid & 31;
    float sv[6] = {s0,s1,s2,s3,s4,s5};
#pragma unroll
    for (int c = 0; c < 6; c++){
        float v = warpSum(sv[c]);
        if (lane == 0) red[c][wid] = v;
    }
    __syncthreads();
    if (tid < 6){
        float v = 0.f;
#pragma unroll
        for (int w = 0; w < 8; w++) v += red[tid][w];
        g_spFeat[k*6 + tid] = v / (float)P;
    }
}

// ---------------- kernel 2: fused assoc + weighted accumulate (per cell block) ----------------
__global__ void __launch_bounds__(256, 1) em_kernel(){
    int k = blockIdx.x, tid = threadIdx.x;
    int kl, kh, kw, y0, ch;
    cellGeom(k, kl, kh, kw, y0, ch);
    int P = 56 * ch;

    __shared__ float sSp[27][6];
    if (tid < 27){
        int dl = tid/9 - 1, dh = (tid/3)%3 - 1, dw = tid%3 - 1;
        int nl = min(max(kl+dl, 0), KL_-1);
        int nh = min(max(kh+dh, 0), KH_-1);
        int nw = min(max(kw+dw, 0), KW_-1);
        int nk = (nl*KH_ + nh)*KW_ + nw;
#pragma unroll
        for (int c = 0; c < 6; c++) sSp[tid][c] = g_spFeat[nk*6 + c];
    }
    unsigned vmask = 0;
#pragma unroll
    for (int j = 0; j < 27; j++){
        int dl = j/9 - 1, dh = (j/3)%3 - 1, dw = j%3 - 1;
        if ((unsigned)(kl+dl) < (unsigned)KL_ &&
            (unsigned)(kh+dh) < (unsigned)KH_ &&
            (unsigned)(kw+dw) < (unsigned)KW_) vmask |= (1u << j);
    }
    __syncthreads();

    float acc[27][7];
#pragma unroll
    for (int j = 0; j < 27; j++)
#pragma unroll
        for (int c = 0; c < 7; c++) acc[j][c] = 0.f;

    const float* gp = &g_pF[(size_t)k*6*CMAX];
#pragma unroll 1
    for (int p = tid; p < P; p += 256){
        float f0 = gp[p],        f1 = gp[CMAX+p],   f2 = gp[2*CMAX+p];
        float f3 = gp[3*CMAX+p], f4 = gp[4*CMAX+p], f5 = gp[5*CMAX+p];
        float e[27];
#pragma unroll
        for (int j = 0; j < 27; j++){
            float t0 = f0 - sSp[j][0]; float dd = t0*t0;
            t0 = f1 - sSp[j][1]; dd += t0*t0;
            t0 = f2 - sSp[j][2]; dd += t0*t0;
            t0 = f3 - sSp[j][3]; dd += t0*t0;
            t0 = f4 - sSp[j][4]; dd += t0*t0;
            t0 = f5 - sSp[j][5]; dd += t0*t0;
            e[j] = (vmask & (1u << j)) ? dd : 1e30f;
        }
        float m = e[0];
#pragma unroll
        for (int j = 1; j < 27; j++) m = fminf(m, e[j]);
        float sum = 0.f;
#pragma unroll
        for (int j = 0; j < 27; j++){ e[j] = __expf(m - e[j]); sum += e[j]; }
        float r = 1.0f / sum;
#pragma unroll
        for (int j = 0; j < 27; j++){
            float a = e[j] * r;
            acc[j][6] += a;
            acc[j][0] += a*f0; acc[j][1] += a*f1; acc[j][2] += a*f2;
            acc[j][3] += a*f3; acc[j][4] += a*f4; acc[j][5] += a*f5;
        }
    }

    __shared__ float sPart[8][190];
    int wid = tid >> 5, lane = tid & 31;
#pragma unroll
    for (int j = 0; j < 27; j++)
#pragma unroll
        for (int c = 0; c < 7; c++){
            float v = warpSum(acc[j][c]);
            if (lane == 0) sPart[wid][j*7 + c] = v;
        }
    __syncthreads();
    if (tid < 189){
        float v = 0.f;
#pragma unroll
        for (int w = 0; w < 8; w++) v += sPart[w][tid];
        g_part[k*189 + tid] = v;   // deterministic: no atomics
    }
}

// ---------------- kernel 3: gather partials -> normalized spFeat ----------------
__global__ void norm_kernel(){
    int k = blockIdx.x, lane = threadIdx.x;  // 32 threads, lanes 0..6 used
    int kl, kh, kw, y0, ch;
    cellGeom(k, kl, kh, kw, y0, ch);
    float v = 0.f;
    if (lane < 7){
#pragma unroll
        for (int j = 0; j < 27; j++){
            int dl = j/9 - 1, dh = (j/3)%3 - 1, dw = j%3 - 1;
            int bl = kl - dl, bh = kh - dh, bw = kw - dw;
            if ((unsigned)bl < (unsigned)KL_ &&
                (unsigned)bh < (unsigned)KH_ &&
                (unsigned)bw < (unsigned)KW_){
                int b = (bl*KH_ + bh)*KW_ + bw;
                v += g_part[b*189 + j*7 + lane];
            }
        }
    }
    float w = __shfl_sync(0xffffffffu, v, 6);
    if (lane < 6) g_spFeat[k*6 + lane] = v / fmaxf(w, 1e-12f);
}

// ---------------- kernel 4: final assoc + argmax + outputs ----------------
__global__ void __launch_bounds__(256) final_kernel(float* __restrict__ outA,
                                                    float* __restrict__ outF){
    int k = blockIdx.x, tid = threadIdx.x;
    int kl, kh, kw, y0, ch;
    cellGeom(k, kl, kh, kw, y0, ch);
    int P = 56 * ch;

    __shared__ float sSp[27][6];
    __shared__ int   sNk[27];
    if (tid < 27){
        int dl = tid/9 - 1, dh = (tid/3)%3 - 1, dw = tid%3 - 1;
        int nl = min(max(kl+dl, 0), KL_-1);
        int nh = min(max(kh+dh, 0), KH_-1);
        int nw = min(max(kw+dw, 0), KW_-1);
        int nk = (nl*KH_ + nh)*KW_ + nw;
        sNk[tid] = nk;
#pragma unroll
        for (int c = 0; c < 6; c++) sSp[tid][c] = g_spFeat[nk*6 + c];
    }
    unsigned vmask = 0;
#pragma unroll
    for (int j = 0; j < 27; j++){
        int dl = j/9 - 1, dh = (j/3)%3 - 1, dw = j%3 - 1;
        if ((unsigned)(kl+dl) < (unsigned)KL_ &&
            (unsigned)(kh+dh) < (unsigned)KH_ &&
            (unsigned)(kw+dw) < (unsigned)KW_) vmask |= (1u << j);
    }
    __syncthreads();

    const float* gp = &g_pF[(size_t)k*6*CMAX];
#pragma unroll 1
    for (int p = tid; p < P; p += 256){
        int lx = p % 14, q = p / 14, ly = q % ch, lt = q / ch;
        int t = 4*kl + lt, y = y0 + ly, x = 14*kw + lx;
        int pix = t*HW_ + y*W_ + x;

        float f0 = gp[p],        f1 = gp[CMAX+p],   f2 = gp[2*CMAX+p];
        float f3 = gp[3*CMAX+p], f4 = gp[4*CMAX+p], f5 = gp[5*CMAX+p];
        float e[27];
#pragma unroll
        for (int j = 0; j < 27; j++){
            float t0 = f0 - sSp[j][0]; float dd = t0*t0;
            t0 = f1 - sSp[j][1]; dd += t0*t0;
            t0 = f2 - sSp[j][2]; dd += t0*t0;
            t0 = f3 - sSp[j][3]; dd += t0*t0;
            t0 = f4 - sSp[j][4]; dd += t0*t0;
            t0 = f5 - sSp[j][5]; dd += t0*t0;
            e[j] = (vmask & (1u << j)) ? dd : 1e30f;
        }
        float m = e[0];
#pragma unroll
        for (int j = 1; j < 27; j++) m = fminf(m, e[j]);
        float sum = 0.f;
#pragma unroll
        for (int j = 0; j < 27; j++){ e[j] = __expf(m - e[j]); sum += e[j]; }
        float r = 1.0f / sum;

        float best = -1.f; int bj = 0;
#pragma unroll
        for (int j = 0; j < 27; j++){
            float a = e[j] * r;
            outA[(size_t)j*NPIX + pix] = a;
            if (a > best){ best = a; bj = j; }
        }
        outF[pix] = (float)sNk[bj];
    }
}

// ---------------- kernel 5: spFeat output (transposed to [c][k]) ----------------
__global__ void spout_kernel(float* __restrict__ outSP){
    int i = blockIdx.x * blockDim.x + threadIdx.x;
    if (i < 6*K_){
        int c = i / K_, k = i - c*K_;
        outSP[i] = g_spFeat[k*6 + c];
    }
}

// ---------------- launcher ----------------
extern "C" void kernel_launch(void* const* d_in, const int* in_sizes, int n_in,
                              void* d_out, int out_size){
    const float* lab = (const float*)d_in[0];
    if (n_in > 1 && in_sizes[0] != 3*NPIX) lab = (const float*)d_in[1];

    float* out   = (float*)d_out;
    float* outPF = out;                          // 6*N   = 5505024
    float* outSP = out + (size_t)6*NPIX;         // 6*K   = 6912
    float* outA  = outSP + 6*K_;                 // 27*N  = 24772608
    float* outF  = outA + (size_t)27*NPIX;       // N     = 917504

    pa_kernel<<<K_, 256>>>(lab, outPF);
    for (int it = 0; it < 4; it++){
        em_kernel<<<K_, 256>>>();
        norm_kernel<<<K_, 32>>>();
    }
    final_kernel<<<K_, 256>>>(outA, outF);
    spout_kernel<<<27, 256>>>(outSP);            // 6912 = 27*256
}